// round 5
// baseline (speedup 1.0000x reference)
#include <cuda_runtime.h>
#include <cuda_bf16.h>
#include <cstdint>

#define B_TOK   8192
#define NE      8
#define DIM     1024
#define TM      128
#define TN      256
#define KC      32
#define NCHUNK  (DIM / KC)
#define ASTRIDE 80
#define A_SUB   (128 * ASTRIDE)         // 10240
#define B_SUB   (256 * ASTRIDE)         // 20480
#define STG     (2 * A_SUB + 2 * B_SUB) // 61440 per stage: Ahi|Alo|Bhi|Blo
#define SMEM_DYN (3 * STG)              // 184320

// ---------------- static device scratch ------------------------------------
__device__ int   g_count[NE];
__device__ int   g_off[NE];
__device__ int   g_tok [NE * B_TOK];
__device__ float g_gate[NE * B_TOK];
#define PAD_ROWS (2 * B_TOK + NE * 128)
__device__ __nv_bfloat16 g_Xhi[(size_t)B_TOK * DIM];
__device__ __nv_bfloat16 g_Xlo[(size_t)B_TOK * DIM];
__device__ __nv_bfloat16 g_Hhi[(size_t)PAD_ROWS * DIM];
__device__ __nv_bfloat16 g_Hlo[(size_t)PAD_ROWS * DIM];
__device__ __nv_bfloat16 g_wthi[(size_t)2 * NE * DIM * DIM];  // [mtx][e][n][k]
__device__ __nv_bfloat16 g_wtlo[(size_t)2 * NE * DIM * DIM];

// ---------------- asm helpers -----------------------------------------------
__device__ __forceinline__ uint32_t smem_u32(const void* p) {
    uint32_t a;
    asm("{ .reg .u64 t; cvta.to.shared.u64 t, %1; cvt.u32.u64 %0, t; }" : "=r"(a) : "l"(p));
    return a;
}
#define LDSM4(r, a) \
    asm volatile("ldmatrix.sync.aligned.m8n8.x4.shared.b16 {%0,%1,%2,%3}, [%4];" \
        : "=r"((r)[0]), "=r"((r)[1]), "=r"((r)[2]), "=r"((r)[3]) : "r"(a))
#define MMA16816(c, a, b0v, b1v) \
    asm volatile("mma.sync.aligned.m16n8k16.row.col.f32.bf16.bf16.f32 " \
        "{%0,%1,%2,%3},{%4,%5,%6,%7},{%8,%9},{%0,%1,%2,%3};" \
        : "+f"((c)[0]), "+f"((c)[1]), "+f"((c)[2]), "+f"((c)[3]) \
        : "r"((a)[0]), "r"((a)[1]), "r"((a)[2]), "r"((a)[3]), "r"(b0v), "r"(b1v))
#define CP16(dst, src, sz) \
    asm volatile("cp.async.cg.shared.global [%0], [%1], 16, %2;" \
        :: "r"(dst), "l"(src), "r"(sz))
#define CP_COMMIT() asm volatile("cp.async.commit_group;" ::: "memory")
#define CP_WAIT1()  asm volatile("cp.async.wait_group 1;" ::: "memory")

// ---------------- small kernels ---------------------------------------------
__global__ void zero_counts_kernel() { if (threadIdx.x < NE) g_count[threadIdx.x] = 0; }

__global__ void offsets_kernel() {
    if (threadIdx.x == 0) {
        int s = 0;
        #pragma unroll
        for (int e = 0; e < NE; e++) { g_off[e] = s; s += (g_count[e] + 127) & ~127; }
    }
}

__global__ void router_kernel(const float* __restrict__ x,
                              const float* __restrict__ rw,
                              const float* __restrict__ rb,
                              float* __restrict__ gating_out) {
    const int warp = threadIdx.x >> 5, lane = threadIdx.x & 31;
    const int t = blockIdx.x * 8 + warp;
    if (t >= B_TOK) return;
    const float* xr = x + (size_t)t * DIM;
    float acc[NE];
    #pragma unroll
    for (int e = 0; e < NE; e++) acc[e] = 0.f;
    for (int i = lane; i < DIM; i += 32) {
        float xv = xr[i];
        const float4* r4 = reinterpret_cast<const float4*>(rw + (size_t)i * NE);
        float4 a = r4[0], b = r4[1];
        acc[0] += xv * a.x; acc[1] += xv * a.y; acc[2] += xv * a.z; acc[3] += xv * a.w;
        acc[4] += xv * b.x; acc[5] += xv * b.y; acc[6] += xv * b.z; acc[7] += xv * b.w;
    }
    #pragma unroll
    for (int e = 0; e < NE; e++)
        #pragma unroll
        for (int off = 16; off; off >>= 1) acc[e] += __shfl_down_sync(0xffffffffu, acc[e], off);
    if (lane == 0) {
        float lg[NE];
        #pragma unroll
        for (int e = 0; e < NE; e++) lg[e] = acc[e] + rb[e];
        int e1 = 0;
        #pragma unroll
        for (int e = 1; e < NE; e++) if (lg[e] > lg[e1]) e1 = e;
        int e2 = -1;
        #pragma unroll
        for (int e = 0; e < NE; e++) { if (e == e1) continue; if (e2 < 0 || lg[e] > lg[e2]) e2 = e; }
        float ex = expf(lg[e2] - lg[e1]);
        float g1 = 1.f / (1.f + ex), g2 = ex / (1.f + ex);
        if (gating_out) {
            float grow[NE];
            #pragma unroll
            for (int e = 0; e < NE; e++) grow[e] = 0.f;
            grow[e1] = g1; grow[e2] = g2;
            float* gp = gating_out + (size_t)t * NE;
            #pragma unroll
            for (int e = 0; e < NE; e++) gp[e] = grow[e];
        }
        int p1 = atomicAdd(&g_count[e1], 1);
        g_tok[e1 * B_TOK + p1] = t; g_gate[e1 * B_TOK + p1] = g1;
        int p2 = atomicAdd(&g_count[e2], 1);
        g_tok[e2 * B_TOK + p2] = t; g_gate[e2 * B_TOK + p2] = g2;
    }
}

// x -> bf16 hi/lo split
__global__ __launch_bounds__(256, 8)
void xsplit_kernel(const float* __restrict__ x) {
    const size_t i4 = (size_t)blockIdx.x * 256 + threadIdx.x;   // float4 index
    const float4 v = reinterpret_cast<const float4*>(x)[i4];
    __nv_bfloat16 h[4], l[4];
    const float* f = reinterpret_cast<const float*>(&v);
    #pragma unroll
    for (int j = 0; j < 4; j++) {
        h[j] = __float2bfloat16(f[j]);
        l[j] = __float2bfloat16(f[j] - __bfloat162float(h[j]));
    }
    reinterpret_cast<uint2*>(g_Xhi)[i4] = *reinterpret_cast<uint2*>(h);
    reinterpret_cast<uint2*>(g_Xlo)[i4] = *reinterpret_cast<uint2*>(l);
}

// transpose + bf16-split weights: w[mtx][e][k][n] -> wt{hi,lo}[mtx][e][n][k]
__global__ __launch_bounds__(256, 4)
void wsplit_kernel(const float* __restrict__ w1, const float* __restrict__ w2) {
    __shared__ float t[32][33];
    const int z = blockIdx.z;
    const float* w = ((z >> 3) ? w2 : w1) + ((size_t)(z & 7) << 20);
    __nv_bfloat16* dh = g_wthi + ((size_t)z << 20);
    __nv_bfloat16* dl = g_wtlo + ((size_t)z << 20);
    const int n0 = blockIdx.x * 32, k0 = blockIdx.y * 32;
    const int tx = threadIdx.x & 31, ty = threadIdx.x >> 5;
    #pragma unroll
    for (int i = 0; i < 4; i++)
        t[ty + 8 * i][tx] = w[(size_t)(k0 + ty + 8 * i) * DIM + n0 + tx];
    __syncthreads();
    #pragma unroll
    for (int i = 0; i < 4; i++) {
        float v = t[tx][ty + 8 * i];
        __nv_bfloat16 h = __float2bfloat16(v);
        __nv_bfloat16 l = __float2bfloat16(v - __bfloat162float(h));
        size_t o = (size_t)(n0 + ty + 8 * i) * DIM + k0 + tx;
        dh[o] = h; dl[o] = l;
    }
}

// ---------------- grouped GEMM: bf16x3, cp.async 3-stage, warp tile 64x64 ----
template <int STAGE>
__global__ __launch_bounds__(256, 1)
void gemm_mma(const float* __restrict__ bias, float* __restrict__ fused) {
    const int e   = blockIdx.z;
    const int cnt = g_count[e];
    const int m0  = blockIdx.y * TM;
    if (m0 >= cnt) return;
    const int n0     = blockIdx.x * TN;
    const int padoff = g_off[e];

    extern __shared__ char smem[];
    const uint32_t sbase = smem_u32(smem);
    const int tid  = threadIdx.x;
    const int lane = tid & 31, warp = tid >> 5;
    const int wm = (warp >> 2) * 64, wn = (warp & 3) * 64;

    // ---- cp.async assignments (fixed per thread) ----
    // A: ids {tid, tid+256}: row = id>>2 (0..127), c16 = id&3
    // B: ids {tid+512*k, k=0..3}: row = id>>2 (0..255), c16 = id&3
    const __nv_bfloat16* aSrc[2];
    uint32_t aDst[2], aSz[2];
    const ptrdiff_t dA = (STAGE == 1)
        ? (const char*)g_Xlo - (const char*)g_Xhi
        : (const char*)g_Hlo - (const char*)g_Hhi;
    #pragma unroll
    for (int j = 0; j < 2; j++) {
        const int id = tid + 256 * j;
        const int row = id >> 2, c16 = id & 3;
        const bool valid = (m0 + row) < cnt;
        size_t rbase;
        if (STAGE == 1)
            rbase = (size_t)(valid ? g_tok[e * B_TOK + m0 + row] : 0) * DIM;
        else
            rbase = (size_t)(padoff + m0 + (valid ? row : 0)) * DIM;
        aSrc[j] = (STAGE == 1 ? g_Xhi : g_Hhi) + rbase + c16 * 8;
        aDst[j] = row * ASTRIDE + c16 * 16;
        aSz[j]  = valid ? 16u : 0u;
    }
    const __nv_bfloat16* bSrc[4];
    uint32_t bDst[4];
    const ptrdiff_t dW = (const char*)g_wtlo - (const char*)g_wthi;
    const size_t wb = ((size_t)((STAGE - 1) * NE + e) << 20) + (size_t)n0 * DIM;
    #pragma unroll
    for (int j = 0; j < 4; j++) {
        const int id = tid + 256 * j;
        const int row = id >> 2, c16 = id & 3;
        bSrc[j] = g_wthi + wb + (size_t)row * DIM + c16 * 8;
        bDst[j] = 2 * A_SUB + row * ASTRIDE + c16 * 16;
    }

    auto issue = [&](int c, int sb3) {
        const int kb = c * KC;                    // element offset
        const uint32_t st = sbase + sb3 * STG;
        #pragma unroll
        for (int j = 0; j < 2; j++) {
            const char* s = (const char*)(aSrc[j] + kb);
            CP16(st + aDst[j],         s,      aSz[j]);
            CP16(st + aDst[j] + A_SUB, s + dA, aSz[j]);
        }
        #pragma unroll
        for (int j = 0; j < 4; j++) {
            const char* s = (const char*)(bSrc[j] + kb);
            CP16(st + bDst[j],         s,      16u);
            CP16(st + bDst[j] + B_SUB, s + dW, 16u);
        }
    };

    float acc[4][8][4];
    #pragma unroll
    for (int i = 0; i < 4; i++)
        #pragma unroll
        for (int j = 0; j < 8; j++)
            #pragma unroll
            for (int k = 0; k < 4; k++) acc[i][j][k] = 0.f;

    issue(0, 0); CP_COMMIT();
    issue(1, 1); CP_COMMIT();

    const uint32_t lrow = lane & 15, lcol = (lane >> 4) * 16;
    int sb3 = 0;            // c % 3
    for (int c = 0; c < NCHUNK; c++) {
        CP_WAIT1();
        __syncthreads();
        {
            int nx = sb3 + 2; if (nx >= 3) nx -= 3;
            if (c + 2 < NCHUNK) issue(c + 2, nx);
            CP_COMMIT();
        }
        const uint32_t sb = sbase + sb3 * STG;
        #pragma unroll
        for (int ks = 0; ks < 2; ks++) {
            const uint32_t ko = ks * 32;
            uint32_t ah[4][4], al[4][4];
            #pragma unroll
            for (int mt = 0; mt < 4; mt++) {
                uint32_t aa = sb + (wm + mt * 16 + lrow) * ASTRIDE + lcol + ko;
                LDSM4(ah[mt], aa);
                LDSM4(al[mt], aa + A_SUB);
            }
            uint32_t bh4[4][4], bl4[4][4];
            #pragma unroll
            for (int p = 0; p < 4; p++) {
                uint32_t ba = sb + 2 * A_SUB + (wn + p * 16 + lrow) * ASTRIDE + lcol + ko;
                LDSM4(bh4[p], ba);
                LDSM4(bl4[p], ba + B_SUB);
            }
            #pragma unroll
            for (int mt = 0; mt < 4; mt++)
                #pragma unroll
                for (int nt = 0; nt < 8; nt++) {
                    const int p = nt >> 1, o = nt & 1;
                    MMA16816(acc[mt][nt], ah[mt], bh4[p][o], bh4[p][o + 2]);
                    MMA16816(acc[mt][nt], ah[mt], bl4[p][o], bl4[p][o + 2]);
                    MMA16816(acc[mt][nt], al[mt], bh4[p][o], bh4[p][o + 2]);
                }
        }
        sb3++; if (sb3 == 3) sb3 = 0;
    }

    // ---- epilogue ----
    const float* bp = bias + (size_t)e * DIM + n0 + wn + (lane & 3) * 2;
    float2 bs[8];
    #pragma unroll
    for (int nt = 0; nt < 8; nt++)
        bs[nt] = *reinterpret_cast<const float2*>(bp + nt * 8);

    #pragma unroll
    for (int mt = 0; mt < 4; mt++) {
        #pragma unroll
        for (int h = 0; h < 2; h++) {
            const int m = m0 + wm + mt * 16 + (lane >> 2) + h * 8;
            if (m >= cnt) continue;
            if (STAGE == 1) {
                size_t rb = (size_t)(padoff + m) * DIM + n0 + wn + (lane & 3) * 2;
                #pragma unroll
                for (int nt = 0; nt < 8; nt++) {
                    float vx = fmaxf(acc[mt][nt][2 * h]     + bs[nt].x, 0.f);
                    float vy = fmaxf(acc[mt][nt][2 * h + 1] + bs[nt].y, 0.f);
                    __nv_bfloat162 hi2, lo2;
                    hi2.x = __float2bfloat16(vx);
                    hi2.y = __float2bfloat16(vy);
                    lo2.x = __float2bfloat16(vx - __bfloat162float(hi2.x));
                    lo2.y = __float2bfloat16(vy - __bfloat162float(hi2.y));
                    *reinterpret_cast<__nv_bfloat162*>(&g_Hhi[rb + nt * 8]) = hi2;
                    *reinterpret_cast<__nv_bfloat162*>(&g_Hlo[rb + nt * 8]) = lo2;
                }
            } else {
                const int tok = g_tok[e * B_TOK + m];
                const float g = g_gate[e * B_TOK + m];
                float* fr = fused + (size_t)tok * DIM + n0 + wn + (lane & 3) * 2;
                #pragma unroll
                for (int nt = 0; nt < 8; nt++) {
                    atomicAdd(&fr[nt * 8],     g * (acc[mt][nt][2 * h]     + bs[nt].x));
                    atomicAdd(&fr[nt * 8 + 1], g * (acc[mt][nt][2 * h + 1] + bs[nt].y));
                }
            }
        }
    }
}

// ---------------- launch ------------------------------------------------------
extern "C" void kernel_launch(void* const* d_in, const int* in_sizes, int n_in,
                              void* d_out, int out_size) {
    const float* x  = (const float*)d_in[0];
    const float* rw = (const float*)d_in[1];
    const float* rb = (const float*)d_in[2];
    const float* w1 = (const float*)d_in[3];
    const float* b1 = (const float*)d_in[4];
    const float* w2 = (const float*)d_in[5];
    const float* b2 = (const float*)d_in[6];

    float* fused = (float*)d_out;
    const size_t fused_elems = (size_t)B_TOK * DIM;
    float* gating_out = nullptr;
    if ((size_t)out_size >= fused_elems + (size_t)B_TOK * NE)
        gating_out = fused + fused_elems;

    cudaFuncSetAttribute(gemm_mma<1>, cudaFuncAttributeMaxDynamicSharedMemorySize, SMEM_DYN);
    cudaFuncSetAttribute(gemm_mma<2>, cudaFuncAttributeMaxDynamicSharedMemorySize, SMEM_DYN);

    cudaMemsetAsync(d_out, 0, fused_elems * sizeof(float), 0);

    zero_counts_kernel<<<1, 32>>>();
    xsplit_kernel<<<(B_TOK * DIM / 4) / 256, 256>>>(x);
    wsplit_kernel<<<dim3(32, 32, 16), 256>>>(w1, w2);
    router_kernel<<<B_TOK / 8, 256>>>(x, rw, rb, gating_out);
    offsets_kernel<<<1, 32>>>();

    dim3 grid(DIM / TN, 64, NE);   // (4, 64, 8); blocks past cnt exit early
    gemm_mma<1><<<grid, 256, SMEM_DYN>>>(b1, fused);
    gemm_mma<2><<<grid, 256, SMEM_DYN>>>(b2, fused);
}

// round 6
// speedup vs baseline: 1.5779x; 1.5779x over previous
#include <cuda_runtime.h>
#include <cuda_fp16.h>
#include <cstdint>

#define B_TOK   8192
#define NE      8
#define DIM     1024
#define TM      128
#define TN      128
#define KC      64
#define NCHUNK  (DIM / KC)
#define A_SUB   16384                  // 128 rows * 128B
#define STG     (3 * A_SUB)            // Ahi | Alo | B
#define SMEM_DYN (3 * STG)             // 147456, 3-stage pipeline

// swizzled byte offset within an operand region: 128B rows, 16B chunks
#define SWZ(row, c16) (((row) << 7) + ((((c16) ^ ((row) & 7))) << 4))

// ---------------- static device scratch ------------------------------------
__device__ int   g_count[NE];
__device__ int   g_off[NE];
__device__ int   g_tok [NE * B_TOK];
__device__ float g_gate[NE * B_TOK];
#define PAD_ROWS (2 * B_TOK + NE * 128)
__device__ __half g_Xhi[(size_t)B_TOK * DIM];
__device__ __half g_Xlo[(size_t)B_TOK * DIM];
__device__ __half g_Hhi[(size_t)PAD_ROWS * DIM];
__device__ __half g_Hlo[(size_t)PAD_ROWS * DIM];
__device__ __half g_wt[(size_t)2 * NE * DIM * DIM];   // [mtx][e][n][k] fp16

// ---------------- asm helpers -----------------------------------------------
__device__ __forceinline__ uint32_t smem_u32(const void* p) {
    uint32_t a;
    asm("{ .reg .u64 t; cvta.to.shared.u64 t, %1; cvt.u32.u64 %0, t; }" : "=r"(a) : "l"(p));
    return a;
}
#define LDSM4(r, a) \
    asm volatile("ldmatrix.sync.aligned.m8n8.x4.shared.b16 {%0,%1,%2,%3}, [%4];" \
        : "=r"((r)[0]), "=r"((r)[1]), "=r"((r)[2]), "=r"((r)[3]) : "r"(a))
#define MMA16816(c, a, b0v, b1v) \
    asm volatile("mma.sync.aligned.m16n8k16.row.col.f32.f16.f16.f32 " \
        "{%0,%1,%2,%3},{%4,%5,%6,%7},{%8,%9},{%0,%1,%2,%3};" \
        : "+f"((c)[0]), "+f"((c)[1]), "+f"((c)[2]), "+f"((c)[3]) \
        : "r"((a)[0]), "r"((a)[1]), "r"((a)[2]), "r"((a)[3]), "r"(b0v), "r"(b1v))
#define CP16(dst, src, sz) \
    asm volatile("cp.async.cg.shared.global [%0], [%1], 16, %2;" \
        :: "r"(dst), "l"(src), "r"(sz))
#define CP_COMMIT() asm volatile("cp.async.commit_group;" ::: "memory")
#define CP_WAIT1()  asm volatile("cp.async.wait_group 1;" ::: "memory")

// ---------------- small kernels ---------------------------------------------
__global__ void zero_counts_kernel() { if (threadIdx.x < NE) g_count[threadIdx.x] = 0; }

__global__ void offsets_kernel() {
    if (threadIdx.x == 0) {
        int s = 0;
        #pragma unroll
        for (int e = 0; e < NE; e++) { g_off[e] = s; s += (g_count[e] + 127) & ~127; }
    }
}

__global__ void router_kernel(const float* __restrict__ x,
                              const float* __restrict__ rw,
                              const float* __restrict__ rb,
                              float* __restrict__ gating_out) {
    const int warp = threadIdx.x >> 5, lane = threadIdx.x & 31;
    const int t = blockIdx.x * 8 + warp;
    if (t >= B_TOK) return;
    const float* xr = x + (size_t)t * DIM;
    float acc[NE];
    #pragma unroll
    for (int e = 0; e < NE; e++) acc[e] = 0.f;
    for (int i = lane; i < DIM; i += 32) {
        float xv = xr[i];
        const float4* r4 = reinterpret_cast<const float4*>(rw + (size_t)i * NE);
        float4 a = r4[0], b = r4[1];
        acc[0] += xv * a.x; acc[1] += xv * a.y; acc[2] += xv * a.z; acc[3] += xv * a.w;
        acc[4] += xv * b.x; acc[5] += xv * b.y; acc[6] += xv * b.z; acc[7] += xv * b.w;
    }
    #pragma unroll
    for (int e = 0; e < NE; e++)
        #pragma unroll
        for (int off = 16; off; off >>= 1) acc[e] += __shfl_down_sync(0xffffffffu, acc[e], off);
    if (lane == 0) {
        float lg[NE];
        #pragma unroll
        for (int e = 0; e < NE; e++) lg[e] = acc[e] + rb[e];
        int e1 = 0;
        #pragma unroll
        for (int e = 1; e < NE; e++) if (lg[e] > lg[e1]) e1 = e;
        int e2 = -1;
        #pragma unroll
        for (int e = 0; e < NE; e++) { if (e == e1) continue; if (e2 < 0 || lg[e] > lg[e2]) e2 = e; }
        float ex = expf(lg[e2] - lg[e1]);
        float g1 = 1.f / (1.f + ex), g2 = ex / (1.f + ex);
        if (gating_out) {
            float grow[NE];
            #pragma unroll
            for (int e = 0; e < NE; e++) grow[e] = 0.f;
            grow[e1] = g1; grow[e2] = g2;
            float* gp = gating_out + (size_t)t * NE;
            #pragma unroll
            for (int e = 0; e < NE; e++) gp[e] = grow[e];
        }
        int p1 = atomicAdd(&g_count[e1], 1);
        g_tok[e1 * B_TOK + p1] = t; g_gate[e1 * B_TOK + p1] = g1;
        int p2 = atomicAdd(&g_count[e2], 1);
        g_tok[e2 * B_TOK + p2] = t; g_gate[e2 * B_TOK + p2] = g2;
    }
}

// x -> fp16 hi/lo split
__global__ __launch_bounds__(256, 8)
void xsplit_kernel(const float* __restrict__ x) {
    const size_t i4 = (size_t)blockIdx.x * 256 + threadIdx.x;
    const float4 v = reinterpret_cast<const float4*>(x)[i4];
    __half h[4], l[4];
    const float* f = reinterpret_cast<const float*>(&v);
    #pragma unroll
    for (int j = 0; j < 4; j++) {
        h[j] = __float2half(f[j]);
        l[j] = __float2half(f[j] - __half2float(h[j]));
    }
    reinterpret_cast<uint2*>(g_Xhi)[i4] = *reinterpret_cast<uint2*>(h);
    reinterpret_cast<uint2*>(g_Xlo)[i4] = *reinterpret_cast<uint2*>(l);
}

// transpose weights to fp16: w[mtx][e][k][n] -> wt[mtx][e][n][k]
__global__ __launch_bounds__(256, 4)
void wsplit_kernel(const float* __restrict__ w1, const float* __restrict__ w2) {
    __shared__ float t[32][33];
    const int z = blockIdx.z;
    const float* w = ((z >> 3) ? w2 : w1) + ((size_t)(z & 7) << 20);
    __half* dh = g_wt + ((size_t)z << 20);
    const int n0 = blockIdx.x * 32, k0 = blockIdx.y * 32;
    const int tx = threadIdx.x & 31, ty = threadIdx.x >> 5;
    #pragma unroll
    for (int i = 0; i < 4; i++)
        t[ty + 8 * i][tx] = w[(size_t)(k0 + ty + 8 * i) * DIM + n0 + tx];
    __syncthreads();
    #pragma unroll
    for (int i = 0; i < 4; i++)
        dh[(size_t)(n0 + ty + 8 * i) * DIM + k0 + tx] = __float2half(t[tx][ty + 8 * i]);
}

// ---------------- grouped GEMM: fp16 2-term, cp.async 3-stage ---------------
template <int STAGE>
__global__ __launch_bounds__(256)
void gemm_mma(const float* __restrict__ bias, float* __restrict__ fused) {
    const int e   = blockIdx.z;
    const int cnt = g_count[e];
    const int m0  = blockIdx.y * TM;
    if (m0 >= cnt) return;
    const int n0     = blockIdx.x * TN;
    const int padoff = g_off[e];

    extern __shared__ char smem[];
    const uint32_t sbase = smem_u32(smem);
    const int tid  = threadIdx.x;
    const int lane = tid & 31, warp = tid >> 5;
    const int wm = (warp >> 2) * 64, wn = (warp & 3) * 32;

    // ---- cp.async assignments: 1024 slots per operand, 4 per thread ----
    // slot id = tid + 256*j : row = id>>3 (0..127), c16 = id&7
    const __half* aSrc[4];
    const __half* bSrc[4];
    uint32_t aDst[4], aSz[4], bDst[4];
    const ptrdiff_t dA = (STAGE == 1)
        ? (const char*)g_Xlo - (const char*)g_Xhi
        : (const char*)g_Hlo - (const char*)g_Hhi;
    const size_t wb = ((size_t)((STAGE - 1) * NE + e) << 20) + (size_t)n0 * DIM;
    #pragma unroll
    for (int j = 0; j < 4; j++) {
        const int id = tid + 256 * j;
        const int row = id >> 3, c16 = id & 7;
        const bool valid = (m0 + row) < cnt;
        size_t rbase;
        if (STAGE == 1)
            rbase = (size_t)(valid ? g_tok[e * B_TOK + m0 + row] : 0) * DIM;
        else
            rbase = (size_t)(padoff + m0 + (valid ? row : 0)) * DIM;
        aSrc[j] = (STAGE == 1 ? g_Xhi : g_Hhi) + rbase + c16 * 8;
        aDst[j] = SWZ(row, c16);
        aSz[j]  = valid ? 16u : 0u;
        bSrc[j] = g_wt + wb + (size_t)row * DIM + c16 * 8;
        bDst[j] = 2 * A_SUB + SWZ(row, c16);
    }

    auto issue = [&](int c, int sb3) {
        const int kb = c * KC;
        const uint32_t st = sbase + sb3 * STG;
        #pragma unroll
        for (int j = 0; j < 4; j++) {
            const char* s = (const char*)(aSrc[j] + kb);
            CP16(st + aDst[j],         s,      aSz[j]);
            CP16(st + aDst[j] + A_SUB, s + dA, aSz[j]);
            CP16(st + bDst[j], (const char*)(bSrc[j] + kb), 16u);
        }
    };

    float acc[4][4][4];
    #pragma unroll
    for (int i = 0; i < 4; i++)
        #pragma unroll
        for (int j = 0; j < 4; j++)
            #pragma unroll
            for (int k = 0; k < 4; k++) acc[i][j][k] = 0.f;

    issue(0, 0); CP_COMMIT();
    issue(1, 1); CP_COMMIT();

    const int lrow = lane & 15, lhalf = lane >> 4;
    int sb3 = 0;
    for (int c = 0; c < NCHUNK; c++) {
        CP_WAIT1();
        __syncthreads();
        {
            int nx = sb3 + 2; if (nx >= 3) nx -= 3;
            if (c + 2 < NCHUNK) issue(c + 2, nx);
            CP_COMMIT();
        }
        const uint32_t sb = sbase + sb3 * STG;
        #pragma unroll
        for (int ks = 0; ks < 4; ks++) {
            const int c16 = ks * 2 + lhalf;
            uint32_t ah[4][4], al[4][4];
            #pragma unroll
            for (int mt = 0; mt < 4; mt++) {
                const int row = wm + mt * 16 + lrow;
                const uint32_t aa = sb + SWZ(row, c16);
                LDSM4(ah[mt], aa);
                LDSM4(al[mt], aa + A_SUB);
            }
            uint32_t bh[2][4];
            #pragma unroll
            for (int p = 0; p < 2; p++) {
                const int row = wn + p * 16 + lrow;
                LDSM4(bh[p], sb + 2 * A_SUB + SWZ(row, c16));
            }
            #pragma unroll
            for (int mt = 0; mt < 4; mt++)
                #pragma unroll
                for (int nt = 0; nt < 4; nt++) {
                    const int p = nt >> 1, o = nt & 1;
                    MMA16816(acc[mt][nt], ah[mt], bh[p][o], bh[p][o + 2]);
                    MMA16816(acc[mt][nt], al[mt], bh[p][o], bh[p][o + 2]);
                }
        }
        sb3++; if (sb3 == 3) sb3 = 0;
    }

    // ---- epilogue ----
    const float* bp = bias + (size_t)e * DIM + n0 + wn + (lane & 3) * 2;
    float2 bs[4];
    #pragma unroll
    for (int nt = 0; nt < 4; nt++)
        bs[nt] = *reinterpret_cast<const float2*>(bp + nt * 8);

    #pragma unroll
    for (int mt = 0; mt < 4; mt++) {
        #pragma unroll
        for (int h = 0; h < 2; h++) {
            const int m = m0 + wm + mt * 16 + (lane >> 2) + h * 8;
            if (m >= cnt) continue;
            if (STAGE == 1) {
                size_t rb = (size_t)(padoff + m) * DIM + n0 + wn + (lane & 3) * 2;
                #pragma unroll
                for (int nt = 0; nt < 4; nt++) {
                    float vx = fmaxf(acc[mt][nt][2 * h]     + bs[nt].x, 0.f);
                    float vy = fmaxf(acc[mt][nt][2 * h + 1] + bs[nt].y, 0.f);
                    __half2 hi2, lo2;
                    hi2.x = __float2half(vx);
                    hi2.y = __float2half(vy);
                    lo2.x = __float2half(vx - __half2float(hi2.x));
                    lo2.y = __float2half(vy - __half2float(hi2.y));
                    *reinterpret_cast<__half2*>(&g_Hhi[rb + nt * 8]) = hi2;
                    *reinterpret_cast<__half2*>(&g_Hlo[rb + nt * 8]) = lo2;
                }
            } else {
                const int tok = g_tok[e * B_TOK + m];
                const float g = g_gate[e * B_TOK + m];
                float* fr = fused + (size_t)tok * DIM + n0 + wn + (lane & 3) * 2;
                #pragma unroll
                for (int nt = 0; nt < 4; nt++) {
                    atomicAdd(&fr[nt * 8],     g * (acc[mt][nt][2 * h]     + bs[nt].x));
                    atomicAdd(&fr[nt * 8 + 1], g * (acc[mt][nt][2 * h + 1] + bs[nt].y));
                }
            }
        }
    }
}

// ---------------- launch ------------------------------------------------------
extern "C" void kernel_launch(void* const* d_in, const int* in_sizes, int n_in,
                              void* d_out, int out_size) {
    const float* x  = (const float*)d_in[0];
    const float* rw = (const float*)d_in[1];
    const float* rb = (const float*)d_in[2];
    const float* w1 = (const float*)d_in[3];
    const float* b1 = (const float*)d_in[4];
    const float* w2 = (const float*)d_in[5];
    const float* b2 = (const float*)d_in[6];

    float* fused = (float*)d_out;
    const size_t fused_elems = (size_t)B_TOK * DIM;
    float* gating_out = nullptr;
    if ((size_t)out_size >= fused_elems + (size_t)B_TOK * NE)
        gating_out = fused + fused_elems;

    cudaFuncSetAttribute(gemm_mma<1>, cudaFuncAttributeMaxDynamicSharedMemorySize, SMEM_DYN);
    cudaFuncSetAttribute(gemm_mma<2>, cudaFuncAttributeMaxDynamicSharedMemorySize, SMEM_DYN);

    cudaMemsetAsync(d_out, 0, fused_elems * sizeof(float), 0);

    zero_counts_kernel<<<1, 32>>>();
    xsplit_kernel<<<(B_TOK * DIM / 4) / 256, 256>>>(x);
    wsplit_kernel<<<dim3(32, 32, 16), 256>>>(w1, w2);
    router_kernel<<<B_TOK / 8, 256>>>(x, rw, rb, gating_out);
    offsets_kernel<<<1, 32>>>();

    dim3 grid(DIM / TN, 64, NE);   // (8, 64, 8); blocks past cnt exit early
    gemm_mma<1><<<grid, 256, SMEM_DYN>>>(b1, fused);
    gemm_mma<2><<<grid, 256, SMEM_DYN>>>(b2, fused);
}